// round 9
// baseline (speedup 1.0000x reference)
#include <cuda_runtime.h>

#define NBATCH 4
#define CCH 256
#define FH 100
#define FW 152
#define HW (FH*FW)           // 15200
#define FWC (FW*CCH)         // 38912
#define NROI 4000
#define HALF_CH 128
#define HALF_OUT (HALF_CH*49)      // 6272 floats, linear 16B-aligned region
#define SMEM_BYTES (HALF_OUT*4)    // 25088 B dynamic

// NHWC scratch (device global: allocation-free scratch per harness rules)
__device__ float g_nhwc[NBATCH * HW * CCH];

// ---------------------------------------------------------------------------
// Kernel A: NCHW -> NHWC transpose. 128ch x 32hw tiles: 3800 blocks,
// 16 independent LDGs per thread (deep MLP). ~15us measured (DRAM floor).
// ---------------------------------------------------------------------------
__global__ __launch_bounds__(256) void transpose_kernel(const float* __restrict__ in) {
    __shared__ float tile[128][33];
    const int b   = blockIdx.z;
    const int hw0 = blockIdx.x * 32;
    const int c0  = blockIdx.y * 128;
    const int x   = threadIdx.x;
    const int y   = threadIdx.y;

    const float* src = in + (size_t)b * CCH * HW + (size_t)(c0 + y) * HW + hw0 + x;
    #pragma unroll
    for (int k = 0; k < 16; k++)
        tile[y + 8*k][x] = __ldcs(src + (size_t)(8*k) * HW);
    __syncthreads();

    float* dst = g_nhwc + (size_t)b * HW * CCH + (size_t)hw0 * CCH + c0 + x;
    #pragma unroll
    for (int k = 0; k < 4; k++) {
        const int hw = y + 8*k;
        #pragma unroll
        for (int m = 0; m < 4; m++)
            dst[(size_t)hw * CCH + 32*m] = tile[x + 32*m][hw];
    }
}

// ---------------------------------------------------------------------------
// Gather one sample row i for channel c; return 7 horizontal pair-sums.
// ---------------------------------------------------------------------------
__device__ __forceinline__ void gather_row(
    int i, const float* __restrict__ fbase,
    const int* s_ws, const int* s_hs,
    const float* s_wf, const float* s_hf,
    const float* s_wm, const float* s_hm,
    float* __restrict__ hsum)
{
    const float* r0 = fbase + s_hs[i] * FWC;
    const float hf = s_hf[i];
    const float hm = s_hm[i];

    float cur[8];
    #pragma unroll
    for (int j = 0; j < 8; j++) {
        const int w0 = s_ws[j];
        float a00 = r0[w0];
        float a01 = r0[w0 + CCH];
        float a10 = r0[w0 + FWC];
        float a11 = r0[w0 + FWC + CCH];
        float wf  = s_wf[j];
        float top = a00 + (a01 - a00) * wf;
        float bot = a10 + (a11 - a10) * wf;
        cur[j] = (top + (bot - top) * hf) * (hm * s_wm[j]);
    }
    #pragma unroll
    for (int j = 0; j < 7; j++) hsum[j] = cur[j] + cur[j+1];
}

// ---------------------------------------------------------------------------
// Kernel B: one 256-thread block per (roi, channel-half).
// BALANCED 4+4 row split with smem seam exchange (replaces the 5+4 split
// that duplicated the seam gather and made g0 the critical path):
//   g0: sample rows 0-3 -> pooled 0-2, stashes row-3 pair-sums in s_seam
//   g1: sample rows 4-7 -> pooled 4-6, keeps row-4 pair-sums in regs,
//       then pooled 3 = 0.25*(s_seam + row-4 sums) after the barrier.
// Longest warp chain: 5 rows -> 4 rows; total LDGs -11%.
// ---------------------------------------------------------------------------
__global__ __launch_bounds__(256) void roi_kernel(
    const float* __restrict__ rois,
    const int*   __restrict__ bids,
    float*       __restrict__ out)
{
    extern __shared__ float s_out[];        // [128][49]
    __shared__ float s_seam[HALF_CH][7];    // row-3 pair-sums, 3.6KB
    __shared__ int   s_ws[8], s_hs[8];
    __shared__ float s_wf[8], s_hf[8], s_wm[8], s_hm[8];

    const int bx   = blockIdx.x;
    const int r    = bx >> 1;
    const int half = bx & 1;
    const int t    = threadIdx.x;
    const int c    = t & (HALF_CH - 1);
    const int g    = t >> 7;           // warps 0-3: g=0, warps 4-7: g=1

    if (t < 8) {
        float x1 = rois[r*4 + 0] * 0.0625f;
        float x2 = rois[r*4 + 2] * 0.0625f;
        float bw = fmaxf(x2 - x1 + 1.0f, 0.0f) * (1.0f / 7.0f);
        float w  = x1 + (float)t * bw;
        s_wm[t]  = (w >= 0.0f && w < (float)FW) ? 1.0f : 0.0f;
        float wsf = fminf(fmaxf(floorf(w), 0.0f), (float)(FW - 2));
        s_ws[t]  = (int)wsf * CCH;     // pre-scaled column offset (floats)
        s_wf[t]  = w - wsf;
    } else if (t < 16) {
        int i = t & 7;
        float y1 = rois[r*4 + 1] * 0.0625f;
        float y2 = rois[r*4 + 3] * 0.0625f;
        float bh = fmaxf(y2 - y1 + 1.0f, 0.0f) * (1.0f / 7.0f);
        float h  = y1 + (float)i * bh;
        s_hm[i]  = (h >= 0.0f && h < (float)FH) ? 1.0f : 0.0f;
        float hsf = fminf(fmaxf(floorf(h), 0.0f), (float)(FH - 2));
        s_hs[i]  = (int)hsf;
        s_hf[i]  = h - hsf;
    }
    __syncthreads();

    const int b = bids[r];
    const float* fbase = g_nhwc + (size_t)b * HW * CCH + half * HALF_CH + c;

    if (g == 0) {
        // rows 0..3 -> pooled 0..2; stash row-3 sums in seam
        float hprev[7], hcur[7];
        gather_row(0, fbase, s_ws, s_hs, s_wf, s_hf, s_wm, s_hm, hprev);
        #pragma unroll
        for (int k = 1; k < 4; ++k) {
            gather_row(k, fbase, s_ws, s_hs, s_wf, s_hf, s_wm, s_hm, hcur);
            int rb = c * 49 + (k - 1) * 7;
            #pragma unroll
            for (int j = 0; j < 7; j++) s_out[rb + j] = 0.25f * (hprev[j] + hcur[j]);
            #pragma unroll
            for (int j = 0; j < 7; j++) hprev[j] = hcur[j];
        }
        #pragma unroll
        for (int j = 0; j < 7; j++) s_seam[c][j] = hprev[j];
    } else {
        // rows 4..7 -> pooled 4..6; keep row-4 sums for pooled 3
        float h4[7], hprev[7], hcur[7];
        gather_row(4, fbase, s_ws, s_hs, s_wf, s_hf, s_wm, s_hm, h4);
        #pragma unroll
        for (int j = 0; j < 7; j++) hprev[j] = h4[j];
        #pragma unroll
        for (int k = 1; k < 4; ++k) {
            int i = 4 + k;
            gather_row(i, fbase, s_ws, s_hs, s_wf, s_hf, s_wm, s_hm, hcur);
            int rb = c * 49 + (i - 1) * 7;
            #pragma unroll
            for (int j = 0; j < 7; j++) s_out[rb + j] = 0.25f * (hprev[j] + hcur[j]);
            #pragma unroll
            for (int j = 0; j < 7; j++) hprev[j] = hcur[j];
        }
        __syncthreads();                       // s_seam ready (g0 done)
        int rb = c * 49 + 3 * 7;
        #pragma unroll
        for (int j = 0; j < 7; j++) s_out[rb + j] = 0.25f * (s_seam[c][j] + h4[j]);
    }
    if (g == 0) __syncthreads();               // matching barrier for g0

    __syncthreads();

    // Coalesced flush: this half's output region is linear in global memory.
    float4*       op = (float4*)(out + (size_t)r * (CCH*49) + half * HALF_OUT);
    const float4* sp = (const float4*)s_out;
    #pragma unroll
    for (int m = t; m < HALF_OUT / 4; m += 256)
        op[m] = sp[m];
}

// ---------------------------------------------------------------------------
extern "C" void kernel_launch(void* const* d_in, const int* in_sizes, int n_in,
                              void* d_out, int out_size) {
    const float* features = (const float*)d_in[0];
    const float* rois     = (const float*)d_in[1];
    const int*   bids     = (const int*)d_in[2];
    float*       out      = (float*)d_out;

    dim3 tgrid(HW / 32, CCH / 128, NBATCH);   // (475, 2, 4) = 3800 blocks
    transpose_kernel<<<tgrid, dim3(32, 8)>>>(features);

    cudaFuncSetAttribute(roi_kernel,
                         cudaFuncAttributeMaxDynamicSharedMemorySize,
                         SMEM_BYTES);
    roi_kernel<<<NROI * 2, 256, SMEM_BYTES>>>(rois, bids, out);
}

// round 10
// speedup vs baseline: 1.1087x; 1.1087x over previous
#include <cuda_runtime.h>
#include <cuda_fp16.h>

#define NBATCH 4
#define CCH 256
#define FH 100
#define FW 152
#define HW (FH*FW)           // 15200
#define FWC (FW*CCH)         // 38912  (element stride, same in halfs)
#define NROI 4000
#define OUT_PER_ROI (CCH*49)       // 12544 floats, linear
#define SMEM_BYTES (OUT_PER_ROI*4) // 50176 B -> 4 CTAs/SM

// NHWC scratch in fp16: 31MB instead of 62MB. Math stays fp32; only the
// scratch storage is half precision (expected rel_err ~1e-4 vs 1e-3 gate).
__device__ __half g_nhwc_h[NBATCH * HW * CCH];

// ---------------------------------------------------------------------------
// Kernel A: NCHW(f32) -> NHWC(fp16) transpose. 128ch x 32hw tiles, 3800
// blocks, 16 independent LDGs/thread. Write volume halves vs f32 scratch.
// ---------------------------------------------------------------------------
__global__ __launch_bounds__(256) void transpose_kernel(const float* __restrict__ in) {
    __shared__ float tile[128][33];
    const int b   = blockIdx.z;
    const int hw0 = blockIdx.x * 32;
    const int c0  = blockIdx.y * 128;
    const int x   = threadIdx.x;
    const int y   = threadIdx.y;

    const float* src = in + (size_t)b * CCH * HW + (size_t)(c0 + y) * HW + hw0 + x;
    #pragma unroll
    for (int k = 0; k < 16; k++)
        tile[y + 8*k][x] = __ldcs(src + (size_t)(8*k) * HW);
    __syncthreads();

    __half* dst = g_nhwc_h + (size_t)b * HW * CCH + (size_t)hw0 * CCH + c0 + x;
    #pragma unroll
    for (int k = 0; k < 4; k++) {
        const int hw = y + 8*k;
        #pragma unroll
        for (int m = 0; m < 4; m++)
            dst[(size_t)hw * CCH + 32*m] = __float2half_rn(tile[x + 32*m][hw]);
    }
}

// ---------------------------------------------------------------------------
// Row-group body: half2 gathers (2 consecutive channels per 32-bit LDG),
// fp32 lerp math, horizontal pair-sum rolling carry (live ~30 floats).
// ---------------------------------------------------------------------------
template<int NR>
__device__ __forceinline__ void process_rows_h2(
    int i0, const __half* __restrict__ fbase, int c0,
    const int* s_ws, const int* s_hs,
    const float* s_wf, const float* s_hf,
    const float* s_wm, const float* s_hm,
    float* s_out)
{
    float2 hprev[7];
    #pragma unroll
    for (int k = 0; k < NR; ++k) {
        const int i = i0 + k;
        const __half* r0 = fbase + s_hs[i] * FWC;
        const float hf = s_hf[i];
        const float hm = s_hm[i];

        float2 cur[8];
        #pragma unroll
        for (int j = 0; j < 8; j++) {
            const int w0 = s_ws[j];
            float2 a00 = __half22float2(*(const half2*)(r0 + w0));
            float2 a01 = __half22float2(*(const half2*)(r0 + w0 + CCH));
            float2 a10 = __half22float2(*(const half2*)(r0 + w0 + FWC));
            float2 a11 = __half22float2(*(const half2*)(r0 + w0 + FWC + CCH));
            float wf = s_wf[j];
            float m  = hm * s_wm[j];
            float tx = a00.x + (a01.x - a00.x) * wf;
            float ty = a00.y + (a01.y - a00.y) * wf;
            float bx = a10.x + (a11.x - a10.x) * wf;
            float by = a10.y + (a11.y - a10.y) * wf;
            cur[j].x = (tx + (bx - tx) * hf) * m;
            cur[j].y = (ty + (by - ty) * hf) * m;
        }

        float2 hcur[7];
        #pragma unroll
        for (int j = 0; j < 7; j++) {
            hcur[j].x = cur[j].x + cur[j+1].x;
            hcur[j].y = cur[j].y + cur[j+1].y;
        }

        if (k > 0) {
            int rb = (i - 1) * 7;
            #pragma unroll
            for (int j = 0; j < 7; j++) {
                s_out[c0 * 49 + rb + j]       = 0.25f * (hprev[j].x + hcur[j].x);
                s_out[(c0 + 1) * 49 + rb + j] = 0.25f * (hprev[j].y + hcur[j].y);
            }
        }
        #pragma unroll
        for (int j = 0; j < 7; j++) hprev[j] = hcur[j];
    }
}

// ---------------------------------------------------------------------------
// Kernel B: one 256-thread block per roi. 128 half2-threads (=256 channels)
// x 2 row-groups, proven 5+4 split (no seam barrier — round 9 showed it
// costs more than the duplicated row-4 gather). half2 halves BOTH the LDG
// count and the L1 wavefront count (unlike float2) at scalar register cost.
// Output staged [256][49] in smem = the roi's linear output block.
// ---------------------------------------------------------------------------
__global__ __launch_bounds__(256) void roi_kernel(
    const float* __restrict__ rois,
    const int*   __restrict__ bids,
    float*       __restrict__ out)
{
    extern __shared__ float s_out[];   // [256][49]
    __shared__ int   s_ws[8], s_hs[8];
    __shared__ float s_wf[8], s_hf[8], s_wm[8], s_hm[8];

    const int r = blockIdx.x;
    const int t = threadIdx.x;
    const int p = t & 127;             // channel-pair index (channels 2p, 2p+1)
    const int g = t >> 7;              // warps 0-3: g=0, warps 4-7: g=1

    if (t < 8) {
        float x1 = rois[r*4 + 0] * 0.0625f;
        float x2 = rois[r*4 + 2] * 0.0625f;
        float bw = fmaxf(x2 - x1 + 1.0f, 0.0f) * (1.0f / 7.0f);
        float w  = x1 + (float)t * bw;
        s_wm[t]  = (w >= 0.0f && w < (float)FW) ? 1.0f : 0.0f;
        float wsf = fminf(fmaxf(floorf(w), 0.0f), (float)(FW - 2));
        s_ws[t]  = (int)wsf * CCH;     // pre-scaled column offset (elements)
        s_wf[t]  = w - wsf;
    } else if (t < 16) {
        int i = t & 7;
        float y1 = rois[r*4 + 1] * 0.0625f;
        float y2 = rois[r*4 + 3] * 0.0625f;
        float bh = fmaxf(y2 - y1 + 1.0f, 0.0f) * (1.0f / 7.0f);
        float h  = y1 + (float)i * bh;
        s_hm[i]  = (h >= 0.0f && h < (float)FH) ? 1.0f : 0.0f;
        float hsf = fminf(fmaxf(floorf(h), 0.0f), (float)(FH - 2));
        s_hs[i]  = (int)hsf;
        s_hf[i]  = h - hsf;
    }
    __syncthreads();

    const int b = bids[r];
    // base of this thread's channel pair (even element offset -> 4B aligned)
    const __half* fbase = g_nhwc_h + (size_t)b * HW * CCH + 2 * p;

    if (g == 0)
        process_rows_h2<5>(0, fbase, 2*p, s_ws, s_hs, s_wf, s_hf, s_wm, s_hm, s_out);
    else
        process_rows_h2<4>(4, fbase, 2*p, s_ws, s_hs, s_wf, s_hf, s_wm, s_hm, s_out);

    __syncthreads();

    // Coalesced flush: the roi's output block is linear in global memory.
    float4*       op = (float4*)(out + (size_t)r * OUT_PER_ROI);
    const float4* sp = (const float4*)s_out;
    #pragma unroll
    for (int m = t; m < OUT_PER_ROI / 4; m += 256)
        op[m] = sp[m];
}

// ---------------------------------------------------------------------------
extern "C" void kernel_launch(void* const* d_in, const int* in_sizes, int n_in,
                              void* d_out, int out_size) {
    const float* features = (const float*)d_in[0];
    const float* rois     = (const float*)d_in[1];
    const int*   bids     = (const int*)d_in[2];
    float*       out      = (float*)d_out;

    dim3 tgrid(HW / 32, CCH / 128, NBATCH);   // (475, 2, 4) = 3800 blocks
    transpose_kernel<<<tgrid, dim3(32, 8)>>>(features);

    cudaFuncSetAttribute(roi_kernel,
                         cudaFuncAttributeMaxDynamicSharedMemorySize,
                         SMEM_BYTES);
    roi_kernel<<<NROI, 256, SMEM_BYTES>>>(rois, bids, out);
}

// round 11
// speedup vs baseline: 1.1799x; 1.0643x over previous
#include <cuda_runtime.h>
#include <cuda_fp16.h>

#define NBATCH 4
#define CCH 256
#define FH 100
#define FW 152
#define HW (FH*FW)           // 15200
#define FWC (FW*CCH)         // 38912  (element stride)
#define NROI 4000
#define OUT_PER_ROI (CCH*49)       // 12544 floats, linear
#define SMEM_BYTES (OUT_PER_ROI*2) // 25088 B (fp16 stage) -> smem no longer binding

// NHWC scratch in fp16 (31MB). Math stays fp32; storage is half.
__device__ __half g_nhwc_h[NBATCH * HW * CCH];

// ---------------------------------------------------------------------------
// Kernel A: NCHW(f32) -> NHWC(fp16) transpose. 128ch x 32hw tiles, 3800
// blocks, 16 independent LDGs/thread. ~13us measured (near DRAM floor).
// ---------------------------------------------------------------------------
__global__ __launch_bounds__(256) void transpose_kernel(const float* __restrict__ in) {
    __shared__ float tile[128][33];
    const int b   = blockIdx.z;
    const int hw0 = blockIdx.x * 32;
    const int c0  = blockIdx.y * 128;
    const int x   = threadIdx.x;
    const int y   = threadIdx.y;

    const float* src = in + (size_t)b * CCH * HW + (size_t)(c0 + y) * HW + hw0 + x;
    #pragma unroll
    for (int k = 0; k < 16; k++)
        tile[y + 8*k][x] = __ldcs(src + (size_t)(8*k) * HW);
    __syncthreads();

    __half* dst = g_nhwc_h + (size_t)b * HW * CCH + (size_t)hw0 * CCH + c0 + x;
    #pragma unroll
    for (int k = 0; k < 4; k++) {
        const int hw = y + 8*k;
        #pragma unroll
        for (int m = 0; m < 4; m++)
            dst[(size_t)hw * CCH + 32*m] = __float2half_rn(tile[x + 32*m][hw]);
    }
}

// ---------------------------------------------------------------------------
// Row-group body: half2 gathers (2 consecutive channels per 32-bit LDG),
// fp32 lerp math, horizontal pair-sum rolling carry; pooled results stored
// to the fp16 smem stage.
// ---------------------------------------------------------------------------
template<int NR>
__device__ __forceinline__ void process_rows_h2(
    int i0, const __half* __restrict__ fbase, int c0,
    const int* s_ws, const int* s_hs,
    const float* s_wf, const float* s_hf,
    const float* s_wm, const float* s_hm,
    __half* s_out)
{
    float2 hprev[7];
    #pragma unroll
    for (int k = 0; k < NR; ++k) {
        const int i = i0 + k;
        const __half* r0 = fbase + s_hs[i] * FWC;
        const float hf = s_hf[i];
        const float hm = s_hm[i];

        float2 cur[8];
        #pragma unroll
        for (int j = 0; j < 8; j++) {
            const int w0 = s_ws[j];
            float2 a00 = __half22float2(*(const half2*)(r0 + w0));
            float2 a01 = __half22float2(*(const half2*)(r0 + w0 + CCH));
            float2 a10 = __half22float2(*(const half2*)(r0 + w0 + FWC));
            float2 a11 = __half22float2(*(const half2*)(r0 + w0 + FWC + CCH));
            float wf = s_wf[j];
            float m  = hm * s_wm[j];
            float tx = a00.x + (a01.x - a00.x) * wf;
            float ty = a00.y + (a01.y - a00.y) * wf;
            float bx = a10.x + (a11.x - a10.x) * wf;
            float by = a10.y + (a11.y - a10.y) * wf;
            cur[j].x = (tx + (bx - tx) * hf) * m;
            cur[j].y = (ty + (by - ty) * hf) * m;
        }

        float2 hcur[7];
        #pragma unroll
        for (int j = 0; j < 7; j++) {
            hcur[j].x = cur[j].x + cur[j+1].x;
            hcur[j].y = cur[j].y + cur[j+1].y;
        }

        if (k > 0) {
            int rb = (i - 1) * 7;
            #pragma unroll
            for (int j = 0; j < 7; j++) {
                s_out[c0 * 49 + rb + j] =
                    __float2half_rn(0.25f * (hprev[j].x + hcur[j].x));
                s_out[(c0 + 1) * 49 + rb + j] =
                    __float2half_rn(0.25f * (hprev[j].y + hcur[j].y));
            }
        }
        #pragma unroll
        for (int j = 0; j < 7; j++) hprev[j] = hcur[j];
    }
}

// ---------------------------------------------------------------------------
// Kernel B: one 256-thread block per roi. 128 half2-threads (=256 channels)
// x 2 row-groups, proven 5+4 split. NEW vs round 10:
//   - output staged in fp16 (25KB instead of 50KB) -> smem allows 8 CTAs
//   - launch_bounds(256,5): 51-reg target (3-reg squeeze from natural 54)
//     -> 5 CTAs/SM = 40 warps, +25% over the 32-warp plateau.
// Flush: uint2 (4 halfs) from smem -> float4 STG, fully coalesced.
// ---------------------------------------------------------------------------
__global__ __launch_bounds__(256, 5) void roi_kernel(
    const float* __restrict__ rois,
    const int*   __restrict__ bids,
    float*       __restrict__ out)
{
    extern __shared__ __half s_out[];   // [256][49] fp16
    __shared__ int   s_ws[8], s_hs[8];
    __shared__ float s_wf[8], s_hf[8], s_wm[8], s_hm[8];

    const int r = blockIdx.x;
    const int t = threadIdx.x;
    const int p = t & 127;             // channel-pair index (channels 2p, 2p+1)
    const int g = t >> 7;              // warps 0-3: g=0, warps 4-7: g=1

    if (t < 8) {
        float x1 = rois[r*4 + 0] * 0.0625f;
        float x2 = rois[r*4 + 2] * 0.0625f;
        float bw = fmaxf(x2 - x1 + 1.0f, 0.0f) * (1.0f / 7.0f);
        float w  = x1 + (float)t * bw;
        s_wm[t]  = (w >= 0.0f && w < (float)FW) ? 1.0f : 0.0f;
        float wsf = fminf(fmaxf(floorf(w), 0.0f), (float)(FW - 2));
        s_ws[t]  = (int)wsf * CCH;     // pre-scaled column offset (elements)
        s_wf[t]  = w - wsf;
    } else if (t < 16) {
        int i = t & 7;
        float y1 = rois[r*4 + 1] * 0.0625f;
        float y2 = rois[r*4 + 3] * 0.0625f;
        float bh = fmaxf(y2 - y1 + 1.0f, 0.0f) * (1.0f / 7.0f);
        float h  = y1 + (float)i * bh;
        s_hm[i]  = (h >= 0.0f && h < (float)FH) ? 1.0f : 0.0f;
        float hsf = fminf(fmaxf(floorf(h), 0.0f), (float)(FH - 2));
        s_hs[i]  = (int)hsf;
        s_hf[i]  = h - hsf;
    }
    __syncthreads();

    const int b = bids[r];
    const __half* fbase = g_nhwc_h + (size_t)b * HW * CCH + 2 * p;

    if (g == 0)
        process_rows_h2<5>(0, fbase, 2*p, s_ws, s_hs, s_wf, s_hf, s_wm, s_hm, s_out);
    else
        process_rows_h2<4>(4, fbase, 2*p, s_ws, s_hs, s_wf, s_hf, s_wm, s_hm, s_out);

    __syncthreads();

    // Coalesced flush: 4 halfs (uint2, 8B-aligned) -> float4 store.
    float4* op = (float4*)(out + (size_t)r * OUT_PER_ROI);
    #pragma unroll
    for (int m = t; m < OUT_PER_ROI / 4; m += 256) {
        const half2* hp = (const half2*)(s_out + 4 * m);
        float2 lo = __half22float2(hp[0]);
        float2 hi = __half22float2(hp[1]);
        op[m] = make_float4(lo.x, lo.y, hi.x, hi.y);
    }
}

// ---------------------------------------------------------------------------
extern "C" void kernel_launch(void* const* d_in, const int* in_sizes, int n_in,
                              void* d_out, int out_size) {
    const float* features = (const float*)d_in[0];
    const float* rois     = (const float*)d_in[1];
    const int*   bids     = (const int*)d_in[2];
    float*       out      = (float*)d_out;

    dim3 tgrid(HW / 32, CCH / 128, NBATCH);   // (475, 2, 4) = 3800 blocks
    transpose_kernel<<<tgrid, dim3(32, 8)>>>(features);

    cudaFuncSetAttribute(roi_kernel,
                         cudaFuncAttributeMaxDynamicSharedMemorySize,
                         SMEM_BYTES);
    roi_kernel<<<NROI, 256, SMEM_BYTES>>>(rois, bids, out);
}